// round 1
// baseline (speedup 1.0000x reference)
#include <cuda_runtime.h>
#include <math.h>

#define BATCH   8
#define NPTS    4096
#define TILE    256
#define BLOCK   256

// Scratch accumulators (no device allocation allowed): [dir][batch]
__device__ double g_accum[2 * BATCH];

__global__ void zero_accum_kernel() {
    int i = threadIdx.x;
    if (i < 2 * BATCH) g_accum[i] = 0.0;
}

// One block = 256 query points of one (direction, batch).
// dir 0: query = x, database = y  -> pc1
// dir 1: query = y, database = x  -> pc2
__global__ void __launch_bounds__(BLOCK) chamfer_kernel(
    const float* __restrict__ x, const float* __restrict__ y)
{
    const int dir = blockIdx.z;
    const int b   = blockIdx.y;
    const float* q  = (dir == 0) ? x : y;
    const float* db = (dir == 0) ? y : x;

    const float* qb  = q  + (size_t)b * NPTS * 3;
    const float* dbb = db + (size_t)b * NPTS * 3;

    const int i = blockIdx.x * BLOCK + threadIdx.x;

    const float qx = qb[i * 3 + 0];
    const float qy = qb[i * 3 + 1];
    const float qz = qb[i * 3 + 2];

    __shared__ float s[TILE * 3];

    float best = 3.4e38f;
    int   bi   = 0;

    for (int t = 0; t < NPTS; t += TILE) {
        __syncthreads();
        // Coalesced load of TILE points (TILE*3 floats) into shared (AoS).
        #pragma unroll
        for (int k = 0; k < 3; k++) {
            s[threadIdx.x + k * BLOCK] = dbb[(size_t)t * 3 + threadIdx.x + k * BLOCK];
        }
        __syncthreads();

        #pragma unroll 8
        for (int j = 0; j < TILE; j++) {
            // All lanes read same address -> shared broadcast, no conflicts.
            float dx = qx - s[j * 3 + 0];
            float dy = qy - s[j * 3 + 1];
            float dz = qz - s[j * 3 + 2];
            float d  = fmaf(dx, dx, fmaf(dy, dy, dz * dz));
            // Strict < keeps FIRST minimum -> matches jnp.argmin tie-breaking.
            if (d < best) { best = d; bi = t + j; }
        }
    }

    // Gather nearest-neighbor coords, compute sum_c |diff_c|^5.
    float nx = dbb[bi * 3 + 0];
    float ny = dbb[bi * 3 + 1];
    float nz = dbb[bi * 3 + 2];
    float ax = fabsf(qx - nx);
    float ay = fabsf(qy - ny);
    float az = fabsf(qz - nz);
    float v = ax * ax * ax * ax * ax
            + ay * ay * ay * ay * ay
            + az * az * az * az * az;

    // Block reduction of v.
    __shared__ float red[BLOCK];
    red[threadIdx.x] = v;
    __syncthreads();
    #pragma unroll
    for (int stride = BLOCK / 2; stride >= 32; stride >>= 1) {
        if (threadIdx.x < stride) red[threadIdx.x] += red[threadIdx.x + stride];
        __syncthreads();
    }
    if (threadIdx.x < 32) {
        float r = red[threadIdx.x];
        #pragma unroll
        for (int off = 16; off > 0; off >>= 1)
            r += __shfl_down_sync(0xFFFFFFFF, r, off);
        if (threadIdx.x == 0)
            atomicAdd(&g_accum[dir * BATCH + b], (double)r);
    }
}

__global__ void final_kernel(float* __restrict__ out) {
    if (threadIdx.x == 0) {
        double acc = 0.0;
        for (int b = 0; b < BATCH; b++) {
            acc += pow(g_accum[b], 0.2);          // pnorm(pc1) for batch b
            acc += pow(g_accum[BATCH + b], 0.2);  // pnorm(pc2) for batch b
        }
        out[0] = (float)(acc / (double)BATCH);
    }
}

extern "C" void kernel_launch(void* const* d_in, const int* in_sizes, int n_in,
                              void* d_out, int out_size)
{
    const float* x = (const float*)d_in[0];
    const float* y = (const float*)d_in[1];
    float* out = (float*)d_out;

    zero_accum_kernel<<<1, 32>>>();

    dim3 grid(NPTS / BLOCK, BATCH, 2);
    chamfer_kernel<<<grid, BLOCK>>>(x, y);

    final_kernel<<<1, 32>>>(out);
}